// round 4
// baseline (speedup 1.0000x reference)
#include <cuda_runtime.h>
#include <cstdint>

#define SQ 1024   // sequence length
#define CC 256    // QDIM == KDIM
#define EE 512    // EMBED
#define BB 8      // batch
#define HH 8      // heads
#define DD 64     // head dim

__device__ float g_Q[BB * EE * SQ];
__device__ float g_K[BB * EE * SQ];
__device__ float g_V[BB * EE * SQ];

__device__ __forceinline__ unsigned tf32c(float x) {
    unsigned r; asm("cvt.rna.tf32.f32 %0,%1;" : "=r"(r) : "f"(x)); return r;
}
__device__ __forceinline__ float tf32f(float x) {
    return __uint_as_float(tf32c(x));
}
__device__ __forceinline__ float ex2f(float x) {
    float r; asm("ex2.approx.ftz.f32 %0,%1;" : "=f"(r) : "f"(x)); return r;
}
__device__ __forceinline__ void mma_tf32(
    float& c0, float& c1, float& c2, float& c3,
    unsigned a0, unsigned a1, unsigned a2, unsigned a3,
    unsigned b0, unsigned b1)
{
    asm volatile(
        "mma.sync.aligned.m16n8k8.row.col.f32.tf32.tf32.f32 "
        "{%0,%1,%2,%3},{%4,%5,%6,%7},{%8,%9},{%0,%1,%2,%3};"
        : "+f"(c0), "+f"(c1), "+f"(c2), "+f"(c3)
        : "r"(a0), "r"(a1), "r"(a2), "r"(a3), "r"(b0), "r"(b1));
}

// ---------------------------------------------------------------------------
// Projection: Y[e][s] = W[e][c] X[c][s] + bias[e]   (tf32 mma)
// CTA 128x128, BK=32. 8 warps as 2(m)x4(n), warp tile 64x32.
// ---------------------------------------------------------------------------
__global__ __launch_bounds__(256) void proj_kernel(
    const float* __restrict__ q_in, const float* __restrict__ k_in,
    const float* __restrict__ wq, const float* __restrict__ biasq,
    const float* __restrict__ wk, const float* __restrict__ biask,
    const float* __restrict__ wv, const float* __restrict__ biasv)
{
    const int z = blockIdx.z;
    const int b = z / 3;
    const int p = z % 3;
    const float* X    = (p == 0 ? q_in : k_in) + (size_t)b * CC * SQ;
    const float* W    = (p == 0) ? wq : (p == 1 ? wk : wv);
    const float* bias = (p == 0) ? biasq : (p == 1 ? biask : biasv);
    float* Y = (p == 0 ? g_Q : (p == 1 ? g_K : g_V)) + (size_t)b * EE * SQ;

    const int m0 = blockIdx.y * 128;
    const int n0 = blockIdx.x * 128;

    __shared__ __align__(16) float Ws[128 * 36];   // [m][k], pad 36
    __shared__ __align__(16) float Xs[32 * 136];   // [k][n], pad 136

    const int tid  = threadIdx.x;
    const int lane = tid & 31;
    const int wid  = tid >> 5;
    const int mw   = (wid & 1) * 64;
    const int nw   = (wid >> 1) * 32;
    const int r    = lane >> 2;
    const int l    = lane & 3;

    float c[4][4][4];
    #pragma unroll
    for (int mt = 0; mt < 4; mt++)
        #pragma unroll
        for (int nt = 0; nt < 4; nt++)
            #pragma unroll
            for (int e = 0; e < 4; e++) c[mt][nt][e] = 0.0f;

    for (int k0 = 0; k0 < CC; k0 += 32) {
        #pragma unroll
        for (int idx = tid; idx < 1024; idx += 256) {
            int row = idx >> 3, k4 = (idx & 7) * 4;
            float4 w4 = *(const float4*)(W + (size_t)(m0 + row) * CC + k0 + k4);
            float* ps = Ws + row * 36 + k4;
            ps[0] = tf32f(w4.x); ps[1] = tf32f(w4.y);
            ps[2] = tf32f(w4.z); ps[3] = tf32f(w4.w);
        }
        #pragma unroll
        for (int idx = tid; idx < 1024; idx += 256) {
            int k = idx >> 5, n4 = (idx & 31) * 4;
            float4 x4 = *(const float4*)(X + (size_t)(k0 + k) * SQ + n0 + n4);
            float* ps = Xs + k * 136 + n4;
            ps[0] = tf32f(x4.x); ps[1] = tf32f(x4.y);
            ps[2] = tf32f(x4.z); ps[3] = tf32f(x4.w);
        }
        __syncthreads();

        #pragma unroll
        for (int ks = 0; ks < 4; ks++) {
            unsigned a[4][4];
            #pragma unroll
            for (int mt = 0; mt < 4; mt++) {
                const float* ap = Ws + (mw + mt * 16 + r) * 36 + ks * 8 + l;
                a[mt][0] = __float_as_uint(ap[0]);
                a[mt][1] = __float_as_uint(ap[8 * 36]);
                a[mt][2] = __float_as_uint(ap[4]);
                a[mt][3] = __float_as_uint(ap[8 * 36 + 4]);
            }
            #pragma unroll
            for (int nt = 0; nt < 4; nt++) {
                const float* bp = Xs + (ks * 8 + l) * 136 + nw + nt * 8 + r;
                unsigned b0 = __float_as_uint(bp[0]);
                unsigned b1 = __float_as_uint(bp[4 * 136]);
                #pragma unroll
                for (int mt = 0; mt < 4; mt++)
                    mma_tf32(c[mt][nt][0], c[mt][nt][1], c[mt][nt][2], c[mt][nt][3],
                             a[mt][0], a[mt][1], a[mt][2], a[mt][3], b0, b1);
            }
        }
        __syncthreads();
    }

    #pragma unroll
    for (int mt = 0; mt < 4; mt++) {
        int e0 = m0 + mw + mt * 16 + r;
        float bv0 = __ldg(bias + e0);
        float bv1 = __ldg(bias + e0 + 8);
        #pragma unroll
        for (int nt = 0; nt < 4; nt++) {
            int s = n0 + nw + nt * 8 + 2 * l;
            *(float2*)(Y + (size_t)e0 * SQ + s) =
                make_float2(c[mt][nt][0] + bv0, c[mt][nt][1] + bv0);
            *(float2*)(Y + (size_t)(e0 + 8) * SQ + s) =
                make_float2(c[mt][nt][2] + bv1, c[mt][nt][3] + bv1);
        }
    }
}

// ---------------------------------------------------------------------------
// Causal flash attention, tf32 mma. Br=128, Bc=64, 256 threads, 2 CTAs/SM.
// Warp owns 16 query rows (softmax warp-local). Smem ~101KB/CTA.
// Pads: Q rows 132, K/V/P rows 68 -> all fragment LDS conflict-free.
// ---------------------------------------------------------------------------
#define QSP 132
#define KSP 68

__global__ __launch_bounds__(256, 2) void attn_kernel(float* __restrict__ out)
{
    extern __shared__ float smf[];
    float* Qs = smf;                    // [64][132]  [d][i]
    float* Ks = Qs + 64 * QSP;          // [64][68]   [d][j]
    float* Vs = Ks + 64 * KSP;          // [64][68]   [d][j]
    float* Ps = Vs + 64 * KSP;          // [128][68]  [i][j]; reused as O [i][d]

    const int qb = 7 - (int)blockIdx.x;  // heavy blocks first
    const int h  = blockIdx.y;
    const int b  = blockIdx.z;

    const float* Qh = g_Q + ((size_t)b * EE + h * DD) * SQ;
    const float* Kh = g_K + ((size_t)b * EE + h * DD) * SQ;
    const float* Vh = g_V + ((size_t)b * EE + h * DD) * SQ;
    float*       Oh = out + ((size_t)b * EE + h * DD) * SQ;

    const int s0   = qb * 128;
    const int tid  = threadIdx.x;
    const int lane = tid & 31;
    const int wid  = tid >> 5;
    const int r    = lane >> 2;
    const int l    = lane & 3;
    const int ib   = wid * 16;

    const float qscale = 0.125f * 1.4426950408889634f;  // 1/sqrt(64)*log2(e)

    // ---- load Q tile once (scaled, tf32)
    for (int t = tid; t < 64 * 32; t += 256) {
        int d = t >> 5, i4 = (t & 31) * 4;
        float4 q = *(const float4*)(Qh + (size_t)d * SQ + s0 + i4);
        float* ps = Qs + d * QSP + i4;
        ps[0] = tf32f(q.x * qscale); ps[1] = tf32f(q.y * qscale);
        ps[2] = tf32f(q.z * qscale); ps[3] = tf32f(q.w * qscale);
    }

    float o[8][4];
    #pragma unroll
    for (int nt = 0; nt < 8; nt++)
        #pragma unroll
        for (int e = 0; e < 4; e++) o[nt][e] = 0.0f;
    float m0r = -1e30f, m1r = -1e30f, l0r = 0.0f, l1r = 0.0f;

    const int nkt = 2 * qb + 2;
    for (int kt = 0; kt < nkt; kt++) {
        __syncthreads();
        const int c0 = kt * 64;
        // ---- stage K and V tiles (64x64 each, tf32)
        for (int t = tid; t < 64 * 16; t += 256) {
            int d = t >> 4, j4 = (t & 15) * 4;
            float4 k4 = *(const float4*)(Kh + (size_t)d * SQ + c0 + j4);
            float* pk = Ks + d * KSP + j4;
            pk[0] = tf32f(k4.x); pk[1] = tf32f(k4.y);
            pk[2] = tf32f(k4.z); pk[3] = tf32f(k4.w);
            float4 v4 = *(const float4*)(Vh + (size_t)d * SQ + c0 + j4);
            float* pv = Vs + d * KSP + j4;
            pv[0] = tf32f(v4.x); pv[1] = tf32f(v4.y);
            pv[2] = tf32f(v4.z); pv[3] = tf32f(v4.w);
        }
        __syncthreads();

        // ---- QK^T: 16 rows x 64 cols per warp
        float sc[8][4];
        #pragma unroll
        for (int nt = 0; nt < 8; nt++)
            #pragma unroll
            for (int e = 0; e < 4; e++) sc[nt][e] = 0.0f;

        #pragma unroll
        for (int ks = 0; ks < 8; ks++) {
            const float* ap = Qs + (ks * 8 + l) * QSP + ib + r;
            unsigned a0 = __float_as_uint(ap[0]);
            unsigned a1 = __float_as_uint(ap[8]);
            unsigned a2 = __float_as_uint(ap[4 * QSP]);
            unsigned a3 = __float_as_uint(ap[4 * QSP + 8]);
            #pragma unroll
            for (int nt = 0; nt < 8; nt++) {
                const float* bp = Ks + (ks * 8 + l) * KSP + nt * 8 + r;
                unsigned b0 = __float_as_uint(bp[0]);
                unsigned b1 = __float_as_uint(bp[4 * KSP]);
                mma_tf32(sc[nt][0], sc[nt][1], sc[nt][2], sc[nt][3],
                         a0, a1, a2, a3, b0, b1);
            }
        }

        // ---- causal mask (only tiles overlapping the diagonal)
        if (kt >= 2 * qb) {
            const int il0 = s0 + ib + r, il1 = il0 + 8;
            #pragma unroll
            for (int nt = 0; nt < 8; nt++) {
                int j = c0 + nt * 8 + 2 * l;
                if (j     > il0) sc[nt][0] = -1e30f;
                if (j + 1 > il0) sc[nt][1] = -1e30f;
                if (j     > il1) sc[nt][2] = -1e30f;
                if (j + 1 > il1) sc[nt][3] = -1e30f;
            }
        }

        // ---- online softmax (rows live in a quad: shfl xor 1,2)
        float mx0 = -1e30f, mx1 = -1e30f;
        #pragma unroll
        for (int nt = 0; nt < 8; nt++) {
            mx0 = fmaxf(mx0, fmaxf(sc[nt][0], sc[nt][1]));
            mx1 = fmaxf(mx1, fmaxf(sc[nt][2], sc[nt][3]));
        }
        mx0 = fmaxf(mx0, __shfl_xor_sync(0xffffffffu, mx0, 1));
        mx0 = fmaxf(mx0, __shfl_xor_sync(0xffffffffu, mx0, 2));
        mx1 = fmaxf(mx1, __shfl_xor_sync(0xffffffffu, mx1, 1));
        mx1 = fmaxf(mx1, __shfl_xor_sync(0xffffffffu, mx1, 2));
        float mn0 = fmaxf(m0r, mx0), mn1 = fmaxf(m1r, mx1);
        float corr0 = ex2f(m0r - mn0), corr1 = ex2f(m1r - mn1);
        m0r = mn0; m1r = mn1;

        float rs0 = 0.0f, rs1 = 0.0f;
        #pragma unroll
        for (int nt = 0; nt < 8; nt++) {
            sc[nt][0] = ex2f(sc[nt][0] - mn0); rs0 += sc[nt][0];
            sc[nt][1] = ex2f(sc[nt][1] - mn0); rs0 += sc[nt][1];
            sc[nt][2] = ex2f(sc[nt][2] - mn1); rs1 += sc[nt][2];
            sc[nt][3] = ex2f(sc[nt][3] - mn1); rs1 += sc[nt][3];
        }
        rs0 += __shfl_xor_sync(0xffffffffu, rs0, 1);
        rs0 += __shfl_xor_sync(0xffffffffu, rs0, 2);
        rs1 += __shfl_xor_sync(0xffffffffu, rs1, 1);
        rs1 += __shfl_xor_sync(0xffffffffu, rs1, 2);
        l0r = l0r * corr0 + rs0;
        l1r = l1r * corr1 + rs1;

        // ---- P -> smem (tf32), warp-local rows
        #pragma unroll
        for (int nt = 0; nt < 8; nt++) {
            int jo = nt * 8 + 2 * l;
            *(float2*)(Ps + (ib + r) * KSP + jo) =
                make_float2(tf32f(sc[nt][0]), tf32f(sc[nt][1]));
            *(float2*)(Ps + (ib + r + 8) * KSP + jo) =
                make_float2(tf32f(sc[nt][2]), tf32f(sc[nt][3]));
        }
        __syncwarp();

        // ---- rescale O accumulators
        #pragma unroll
        for (int nt = 0; nt < 8; nt++) {
            o[nt][0] *= corr0; o[nt][1] *= corr0;
            o[nt][2] *= corr1; o[nt][3] *= corr1;
        }

        // ---- PV: 16 rows x 64 d per warp, K = 64 j
        #pragma unroll
        for (int ks = 0; ks < 8; ks++) {
            const float* ap = Ps + (ib + r) * KSP + ks * 8 + l;
            unsigned a0 = __float_as_uint(ap[0]);
            unsigned a1 = __float_as_uint(ap[8 * KSP]);
            unsigned a2 = __float_as_uint(ap[4]);
            unsigned a3 = __float_as_uint(ap[8 * KSP + 4]);
            #pragma unroll
            for (int nt = 0; nt < 8; nt++) {
                const float* bp = Vs + (nt * 8 + r) * KSP + ks * 8 + l;
                unsigned b0 = __float_as_uint(bp[0]);
                unsigned b1 = __float_as_uint(bp[4]);
                mma_tf32(o[nt][0], o[nt][1], o[nt][2], o[nt][3],
                         a0, a1, a2, a3, b0, b1);
            }
        }
    }

    // ---- epilogue: normalize, stage O as [i][d] in Ps, coalesced STG
    float inv0 = 1.0f / l0r, inv1 = 1.0f / l1r;
    __syncthreads();
    #pragma unroll
    for (int nt = 0; nt < 8; nt++) {
        int d = nt * 8 + 2 * l;
        float* p0 = Ps + (ib + r) * KSP + d;
        float* p1 = Ps + (ib + r + 8) * KSP + d;
        p0[0] = o[nt][0] * inv0; p0[1] = o[nt][1] * inv0;
        p1[0] = o[nt][2] * inv1; p1[1] = o[nt][3] * inv1;
    }
    __syncthreads();

    const int dcol = tid & 63;
    const int iblk = tid >> 6;
    #pragma unroll
    for (int g = 0; g < 8; g++) {
        int i4 = iblk * 32 + g * 4;
        float4 w;
        w.x = Ps[(i4 + 0) * KSP + dcol];
        w.y = Ps[(i4 + 1) * KSP + dcol];
        w.z = Ps[(i4 + 2) * KSP + dcol];
        w.w = Ps[(i4 + 3) * KSP + dcol];
        *(float4*)(Oh + (size_t)dcol * SQ + s0 + i4) = w;
    }
}

// ---------------------------------------------------------------------------
extern "C" void kernel_launch(void* const* d_in, const int* in_sizes, int n_in,
                              void* d_out, int out_size)
{
    const float* query = (const float*)d_in[0];
    const float* key   = (const float*)d_in[1];
    const float* Wq    = (const float*)d_in[2];
    const float* bq    = (const float*)d_in[3];
    const float* Wk    = (const float*)d_in[4];
    const float* bk    = (const float*)d_in[5];
    const float* Wv    = (const float*)d_in[6];
    const float* bv    = (const float*)d_in[7];

    dim3 g1(SQ / 128, EE / 128, BB * 3);
    proj_kernel<<<g1, 256>>>(query, key, Wq, bq, Wk, bk, Wv, bv);

    const int attn_smem = (64 * QSP + 64 * KSP * 2 + 128 * KSP) * 4;  // 103424
    cudaFuncSetAttribute(attn_kernel,
                         cudaFuncAttributeMaxDynamicSharedMemorySize, attn_smem);
    dim3 g2(8, HH, BB);
    attn_kernel<<<g2, 256, attn_smem>>>((float*)d_out);
}

// round 5
// speedup vs baseline: 1.1325x; 1.1325x over previous
#include <cuda_runtime.h>
#include <cstdint>

#define SQ 1024   // sequence length
#define CC 256    // QDIM == KDIM
#define EE 512    // EMBED
#define BB 8      // batch
#define HH 8      // heads
#define DD 64     // head dim

__device__ float g_Q[BB * EE * SQ];
__device__ float g_K[BB * EE * SQ];
__device__ float g_V[BB * EE * SQ];

__device__ __forceinline__ unsigned tf32c(float x) {
    unsigned r; asm("cvt.rna.tf32.f32 %0,%1;" : "=r"(r) : "f"(x)); return r;
}
__device__ __forceinline__ float tf32f(float x) {
    return __uint_as_float(tf32c(x));
}
__device__ __forceinline__ float ex2f(float x) {
    float r; asm("ex2.approx.ftz.f32 %0,%1;" : "=f"(r) : "f"(x)); return r;
}
__device__ __forceinline__ void mma_tf32(
    float& c0, float& c1, float& c2, float& c3,
    unsigned a0, unsigned a1, unsigned a2, unsigned a3,
    unsigned b0, unsigned b1)
{
    asm volatile(
        "mma.sync.aligned.m16n8k8.row.col.f32.tf32.tf32.f32 "
        "{%0,%1,%2,%3},{%4,%5,%6,%7},{%8,%9},{%0,%1,%2,%3};"
        : "+f"(c0), "+f"(c1), "+f"(c2), "+f"(c3)
        : "r"(a0), "r"(a1), "r"(a2), "r"(a3), "r"(b0), "r"(b1));
}

// ---------------------------------------------------------------------------
// Projection: Y[e][s] = W[e][c] X[c][s] + bias[e]   (tf32 mma)
// CTA 128x128, BK=32. 8 warps as 2(m)x4(n), warp tile 64x32.
// ---------------------------------------------------------------------------
__global__ __launch_bounds__(256) void proj_kernel(
    const float* __restrict__ q_in, const float* __restrict__ k_in,
    const float* __restrict__ wq, const float* __restrict__ biasq,
    const float* __restrict__ wk, const float* __restrict__ biask,
    const float* __restrict__ wv, const float* __restrict__ biasv)
{
    const int z = blockIdx.z;
    const int b = z / 3;
    const int p = z % 3;
    const float* X    = (p == 0 ? q_in : k_in) + (size_t)b * CC * SQ;
    const float* W    = (p == 0) ? wq : (p == 1 ? wk : wv);
    const float* bias = (p == 0) ? biasq : (p == 1 ? biask : biasv);
    float* Y = (p == 0 ? g_Q : (p == 1 ? g_K : g_V)) + (size_t)b * EE * SQ;

    const int m0 = blockIdx.y * 128;
    const int n0 = blockIdx.x * 128;

    __shared__ __align__(16) float Ws[128 * 36];   // [m][k], pad 36
    __shared__ __align__(16) float Xs[32 * 136];   // [k][n], pad 136

    const int tid  = threadIdx.x;
    const int lane = tid & 31;
    const int wid  = tid >> 5;
    const int mw   = (wid & 1) * 64;
    const int nw   = (wid >> 1) * 32;
    const int r    = lane >> 2;
    const int l    = lane & 3;

    float c[4][4][4];
    #pragma unroll
    for (int mt = 0; mt < 4; mt++)
        #pragma unroll
        for (int nt = 0; nt < 4; nt++)
            #pragma unroll
            for (int e = 0; e < 4; e++) c[mt][nt][e] = 0.0f;

    for (int k0 = 0; k0 < CC; k0 += 32) {
        #pragma unroll
        for (int idx = tid; idx < 1024; idx += 256) {
            int row = idx >> 3, k4 = (idx & 7) * 4;
            float4 w4 = *(const float4*)(W + (size_t)(m0 + row) * CC + k0 + k4);
            float* ps = Ws + row * 36 + k4;
            ps[0] = tf32f(w4.x); ps[1] = tf32f(w4.y);
            ps[2] = tf32f(w4.z); ps[3] = tf32f(w4.w);
        }
        #pragma unroll
        for (int idx = tid; idx < 1024; idx += 256) {
            int k = idx >> 5, n4 = (idx & 31) * 4;
            float4 x4 = *(const float4*)(X + (size_t)(k0 + k) * SQ + n0 + n4);
            float* ps = Xs + k * 136 + n4;
            ps[0] = tf32f(x4.x); ps[1] = tf32f(x4.y);
            ps[2] = tf32f(x4.z); ps[3] = tf32f(x4.w);
        }
        __syncthreads();

        #pragma unroll
        for (int ks = 0; ks < 4; ks++) {
            unsigned a[4][4];
            #pragma unroll
            for (int mt = 0; mt < 4; mt++) {
                const float* ap = Ws + (mw + mt * 16 + r) * 36 + ks * 8 + l;
                a[mt][0] = __float_as_uint(ap[0]);
                a[mt][1] = __float_as_uint(ap[8 * 36]);
                a[mt][2] = __float_as_uint(ap[4]);
                a[mt][3] = __float_as_uint(ap[8 * 36 + 4]);
            }
            #pragma unroll
            for (int nt = 0; nt < 4; nt++) {
                const float* bp = Xs + (ks * 8 + l) * 136 + nw + nt * 8 + r;
                unsigned b0 = __float_as_uint(bp[0]);
                unsigned b1 = __float_as_uint(bp[4 * 136]);
                #pragma unroll
                for (int mt = 0; mt < 4; mt++)
                    mma_tf32(c[mt][nt][0], c[mt][nt][1], c[mt][nt][2], c[mt][nt][3],
                             a[mt][0], a[mt][1], a[mt][2], a[mt][3], b0, b1);
            }
        }
        __syncthreads();
    }

    #pragma unroll
    for (int mt = 0; mt < 4; mt++) {
        int e0 = m0 + mw + mt * 16 + r;
        float bv0 = __ldg(bias + e0);
        float bv1 = __ldg(bias + e0 + 8);
        #pragma unroll
        for (int nt = 0; nt < 4; nt++) {
            int s = n0 + nw + nt * 8 + 2 * l;
            *(float2*)(Y + (size_t)e0 * SQ + s) =
                make_float2(c[mt][nt][0] + bv0, c[mt][nt][1] + bv0);
            *(float2*)(Y + (size_t)(e0 + 8) * SQ + s) =
                make_float2(c[mt][nt][2] + bv1, c[mt][nt][3] + bv1);
        }
    }
}

// ---------------------------------------------------------------------------
// Causal flash attention, tf32 mma. Br=Bc=128, 512 threads.
// 16 warps: (wi, wj) = warp owns 16 query rows x 64 key cols.
// Each j-half keeps its own online softmax (m, l, partial O); the two halves
// are merged once after the loop (split-KV combine). Smem 171KB, 1 CTA/SM.
// ---------------------------------------------------------------------------
#define QKP 136
#define VPP 132

__global__ __launch_bounds__(512, 1) void attn_kernel(float* __restrict__ out)
{
    extern __shared__ float smf[];
    float* Qs = smf;                    // [64][136]  [d][i]; reused as O [i][d] pad 68
    float* Ks = Qs + 64 * QKP;          // [64][136]  [d][j]
    float* Vs = Ks + 64 * QKP;          // [64][132]  [d][j]
    float* Ps = Vs + 64 * VPP;          // [128][132] [i][j]; reused as combine buf
    __shared__ float Mx1[128];
    __shared__ float Ls1[128];

    const int qb = 7 - (int)blockIdx.x;  // heavy blocks first
    const int h  = blockIdx.y;
    const int b  = blockIdx.z;

    const float* Qh = g_Q + ((size_t)b * EE + h * DD) * SQ;
    const float* Kh = g_K + ((size_t)b * EE + h * DD) * SQ;
    const float* Vh = g_V + ((size_t)b * EE + h * DD) * SQ;
    float*       Oh = out + ((size_t)b * EE + h * DD) * SQ;

    const int s0   = qb * 128;
    const int tid  = threadIdx.x;
    const int lane = tid & 31;
    const int wid  = tid >> 5;
    const int wi   = wid & 7;
    const int wj   = wid >> 3;
    const int r    = lane >> 2;
    const int l    = lane & 3;
    const int ib   = wi * 16;
    const int jb   = wj * 64;

    const float qscale = 0.125f * 1.4426950408889634f;  // 1/sqrt(64)*log2(e)

    // ---- load Q tile once (scaled, tf32)
    for (int t = tid; t < 64 * 32; t += 512) {
        int d = t >> 5, i4 = (t & 31) * 4;
        float4 q = *(const float4*)(Qh + (size_t)d * SQ + s0 + i4);
        float* ps = Qs + d * QKP + i4;
        ps[0] = tf32f(q.x * qscale); ps[1] = tf32f(q.y * qscale);
        ps[2] = tf32f(q.z * qscale); ps[3] = tf32f(q.w * qscale);
    }

    float o[8][4];
    #pragma unroll
    for (int nt = 0; nt < 8; nt++)
        #pragma unroll
        for (int e = 0; e < 4; e++) o[nt][e] = 0.0f;
    float mA = -1e30f, mB = -1e30f, lA = 0.0f, lB = 0.0f;

    for (int kb = 0; kb <= qb; kb++) {
        __syncthreads();
        const int c0 = kb * 128;
        // ---- stage K and V tiles (64 x 128 each, tf32)
        for (int t = tid; t < 64 * 32; t += 512) {
            int d = t >> 5, j4 = (t & 31) * 4;
            float4 k4 = *(const float4*)(Kh + (size_t)d * SQ + c0 + j4);
            float* pk = Ks + d * QKP + j4;
            pk[0] = tf32f(k4.x); pk[1] = tf32f(k4.y);
            pk[2] = tf32f(k4.z); pk[3] = tf32f(k4.w);
            float4 v4 = *(const float4*)(Vh + (size_t)d * SQ + c0 + j4);
            float* pv = Vs + d * VPP + j4;
            pv[0] = tf32f(v4.x); pv[1] = tf32f(v4.y);
            pv[2] = tf32f(v4.z); pv[3] = tf32f(v4.w);
        }
        __syncthreads();

        // ---- QK^T: 16 rows x 64 cols per warp
        float sc[8][4];
        #pragma unroll
        for (int nt = 0; nt < 8; nt++)
            #pragma unroll
            for (int e = 0; e < 4; e++) sc[nt][e] = 0.0f;

        #pragma unroll
        for (int ks = 0; ks < 8; ks++) {
            const float* ap = Qs + (ks * 8 + l) * QKP + ib + r;
            unsigned a0 = __float_as_uint(ap[0]);
            unsigned a1 = __float_as_uint(ap[8]);
            unsigned a2 = __float_as_uint(ap[4 * QKP]);
            unsigned a3 = __float_as_uint(ap[4 * QKP + 8]);
            #pragma unroll
            for (int nt = 0; nt < 8; nt++) {
                const float* bp = Ks + (ks * 8 + l) * QKP + jb + nt * 8 + r;
                unsigned b0 = __float_as_uint(bp[0]);
                unsigned b1 = __float_as_uint(bp[4 * QKP]);
                mma_tf32(sc[nt][0], sc[nt][1], sc[nt][2], sc[nt][3],
                         a0, a1, a2, a3, b0, b1);
            }
        }

        // ---- causal mask on the diagonal block
        if (kb == qb) {
            const int il0 = s0 + ib + r, il1 = il0 + 8;
            #pragma unroll
            for (int nt = 0; nt < 8; nt++) {
                int j = c0 + jb + nt * 8 + 2 * l;
                if (j     > il0) sc[nt][0] = -1e30f;
                if (j + 1 > il0) sc[nt][1] = -1e30f;
                if (j     > il1) sc[nt][2] = -1e30f;
                if (j + 1 > il1) sc[nt][3] = -1e30f;
            }
        }

        // ---- online softmax over this warp's 64-col half (quad shuffles)
        float mx0 = -1e30f, mx1 = -1e30f;
        #pragma unroll
        for (int nt = 0; nt < 8; nt++) {
            mx0 = fmaxf(mx0, fmaxf(sc[nt][0], sc[nt][1]));
            mx1 = fmaxf(mx1, fmaxf(sc[nt][2], sc[nt][3]));
        }
        mx0 = fmaxf(mx0, __shfl_xor_sync(0xffffffffu, mx0, 1));
        mx0 = fmaxf(mx0, __shfl_xor_sync(0xffffffffu, mx0, 2));
        mx1 = fmaxf(mx1, __shfl_xor_sync(0xffffffffu, mx1, 1));
        mx1 = fmaxf(mx1, __shfl_xor_sync(0xffffffffu, mx1, 2));
        float mnA = fmaxf(mA, mx0), mnB = fmaxf(mB, mx1);
        float corrA = ex2f(mA - mnA), corrB = ex2f(mB - mnB);
        mA = mnA; mB = mnB;

        float rsA = 0.0f, rsB = 0.0f;
        #pragma unroll
        for (int nt = 0; nt < 8; nt++) {
            sc[nt][0] = ex2f(sc[nt][0] - mnA); rsA += sc[nt][0];
            sc[nt][1] = ex2f(sc[nt][1] - mnA); rsA += sc[nt][1];
            sc[nt][2] = ex2f(sc[nt][2] - mnB); rsB += sc[nt][2];
            sc[nt][3] = ex2f(sc[nt][3] - mnB); rsB += sc[nt][3];
        }
        rsA += __shfl_xor_sync(0xffffffffu, rsA, 1);
        rsA += __shfl_xor_sync(0xffffffffu, rsA, 2);
        rsB += __shfl_xor_sync(0xffffffffu, rsB, 1);
        rsB += __shfl_xor_sync(0xffffffffu, rsB, 2);
        lA = lA * corrA + rsA;
        lB = lB * corrB + rsB;

        // ---- P -> smem (tf32), warp-local rows/cols
        #pragma unroll
        for (int nt = 0; nt < 8; nt++) {
            int jo = jb + nt * 8 + 2 * l;
            *(float2*)(Ps + (ib + r) * VPP + jo) =
                make_float2(tf32f(sc[nt][0]), tf32f(sc[nt][1]));
            *(float2*)(Ps + (ib + r + 8) * VPP + jo) =
                make_float2(tf32f(sc[nt][2]), tf32f(sc[nt][3]));
        }
        __syncwarp();

        // ---- rescale O partials
        #pragma unroll
        for (int nt = 0; nt < 8; nt++) {
            o[nt][0] *= corrA; o[nt][1] *= corrA;
            o[nt][2] *= corrB; o[nt][3] *= corrB;
        }

        // ---- PV over this warp's j-half: 16 rows x 64 d
        #pragma unroll
        for (int ks = 0; ks < 8; ks++) {
            const float* ap = Ps + (ib + r) * VPP + jb + ks * 8 + l;
            unsigned a0 = __float_as_uint(ap[0]);
            unsigned a1 = __float_as_uint(ap[8 * VPP]);
            unsigned a2 = __float_as_uint(ap[4]);
            unsigned a3 = __float_as_uint(ap[8 * VPP + 4]);
            #pragma unroll
            for (int nt = 0; nt < 8; nt++) {
                const float* bp = Vs + (nt * 8 + r) * VPP + jb + ks * 8 + l;
                unsigned b0 = __float_as_uint(bp[0]);
                unsigned b1 = __float_as_uint(bp[4]);
                mma_tf32(o[nt][0], o[nt][1], o[nt][2], o[nt][3],
                         a0, a1, a2, a3, b0, b1);
            }
        }
    }

    // ---- merge the two j-halves (split-KV combine), then write out
    __syncthreads();
    if (wj == 1) {
        float* cb = Ps + (wi * 32 + lane) * 32;
        #pragma unroll
        for (int nt = 0; nt < 8; nt++) {
            cb[nt * 4 + 0] = o[nt][0]; cb[nt * 4 + 1] = o[nt][1];
            cb[nt * 4 + 2] = o[nt][2]; cb[nt * 4 + 3] = o[nt][3];
        }
        if (l == 0) {
            Mx1[ib + r] = mA;      Ls1[ib + r] = lA;
            Mx1[ib + r + 8] = mB;  Ls1[ib + r + 8] = lB;
        }
    }
    __syncthreads();
    if (wj == 0) {
        const float* cb = Ps + (wi * 32 + lane) * 32;
        float mA1 = Mx1[ib + r],     lA1 = Ls1[ib + r];
        float mB1 = Mx1[ib + r + 8], lB1 = Ls1[ib + r + 8];
        float mAn = fmaxf(mA, mA1), mBn = fmaxf(mB, mB1);
        float cA0 = ex2f(mA - mAn),  cA1 = ex2f(mA1 - mAn);
        float cB0 = ex2f(mB - mBn),  cB1 = ex2f(mB1 - mBn);
        float invA = 1.0f / (lA * cA0 + lA1 * cA1);
        float invB = 1.0f / (lB * cB0 + lB1 * cB1);
        float sA0 = cA0 * invA, sA1 = cA1 * invA;
        float sB0 = cB0 * invB, sB1 = cB1 * invB;
        float* Os = Qs;  // [128][68]
        #pragma unroll
        for (int nt = 0; nt < 8; nt++) {
            int d = nt * 8 + 2 * l;
            float* p0 = Os + (ib + r) * 68 + d;
            float* p1 = Os + (ib + r + 8) * 68 + d;
            p0[0] = o[nt][0] * sA0 + cb[nt * 4 + 0] * sA1;
            p0[1] = o[nt][1] * sA0 + cb[nt * 4 + 1] * sA1;
            p1[0] = o[nt][2] * sB0 + cb[nt * 4 + 2] * sB1;
            p1[1] = o[nt][3] * sB0 + cb[nt * 4 + 3] * sB1;
        }
    }
    __syncthreads();

    const float* Os = Qs;
    const int dcol = tid & 63;
    const int iblk = tid >> 6;   // 0..7
    #pragma unroll
    for (int g = 0; g < 4; g++) {
        int i4 = iblk * 16 + g * 4;
        float4 w;
        w.x = Os[(i4 + 0) * 68 + dcol];
        w.y = Os[(i4 + 1) * 68 + dcol];
        w.z = Os[(i4 + 2) * 68 + dcol];
        w.w = Os[(i4 + 3) * 68 + dcol];
        *(float4*)(Oh + (size_t)dcol * SQ + s0 + i4) = w;
    }
}

// ---------------------------------------------------------------------------
extern "C" void kernel_launch(void* const* d_in, const int* in_sizes, int n_in,
                              void* d_out, int out_size)
{
    const float* query = (const float*)d_in[0];
    const float* key   = (const float*)d_in[1];
    const float* Wq    = (const float*)d_in[2];
    const float* bq    = (const float*)d_in[3];
    const float* Wk    = (const float*)d_in[4];
    const float* bk    = (const float*)d_in[5];
    const float* Wv    = (const float*)d_in[6];
    const float* bv    = (const float*)d_in[7];

    dim3 g1(SQ / 128, EE / 128, BB * 3);
    proj_kernel<<<g1, 256>>>(query, key, Wq, bq, Wk, bk, Wv, bv);

    const int attn_smem = (64 * QKP * 2 + 64 * VPP + 128 * VPP) * 4;  // 171008
    cudaFuncSetAttribute(attn_kernel,
                         cudaFuncAttributeMaxDynamicSharedMemorySize, attn_smem);
    dim3 g2(8, HH, BB);
    attn_kernel<<<g2, 512, attn_smem>>>((float*)d_out);
}